// round 4
// baseline (speedup 1.0000x reference)
#include <cuda_runtime.h>
#include <cstdint>

#define FULLMASK 0xffffffffu

constexpr int B_   = 64;
constexpr int N_   = 1024;
constexpr int D_   = 64;
constexpr int NNODES = B_ * N_;          // 65536
constexpr int EDGES  = 1 << 20;          // 1,048,576
constexpr int ROW_WORDS = N_ / 32;       // 32 words per adjacency row
constexpr int ADJ_WORDS = NNODES * ROW_WORDS;  // 2,097,152 (8 MB)

// Scratch (no allocations allowed in kernel_launch)
__device__ unsigned g_adj[ADJ_WORDS];
__device__ unsigned g_pooled[B_ * D_];   // mapped-uint max accumulator
__device__ int g_is64;

// Order-preserving float <-> uint mapping for atomicMax on floats
__device__ __forceinline__ unsigned fmap(float f) {
    unsigned u = __float_as_uint(f);
    return (u & 0x80000000u) ? ~u : (u | 0x80000000u);
}
__device__ __forceinline__ float funmap(unsigned u) {
    return (u & 0x80000000u) ? __uint_as_float(u ^ 0x80000000u)
                             : __uint_as_float(~u);
}

// ---------------------------------------------------------------------------
// 0) Detect whether edge_index is int64 or int32 (JAX x64 config ambiguity).
//    True int64 node ids are all <= 65535; int32 data reinterpreted as int64
//    produces huge values with overwhelming probability.
// ---------------------------------------------------------------------------
__global__ void k_detect(const void* ei) {
    const long long* p = (const long long*)ei;
    int is64 = 1;
    for (int i = 0; i < 16; i++) {
        long long v = p[i];
        if (v < 0 || v > 65535) is64 = 0;
    }
    g_is64 = is64;
}

// ---------------------------------------------------------------------------
// 1) Clear bitmap + pooled accumulator (vectorized)
// ---------------------------------------------------------------------------
__global__ void k_clear() {
    unsigned idx = blockIdx.x * blockDim.x + threadIdx.x;   // uint4 index
    const uint4 z = make_uint4(0, 0, 0, 0);
    constexpr unsigned ADJ_V4 = ADJ_WORDS / 4;              // 524288
    constexpr unsigned POOL_V4 = (B_ * D_) / 4;             // 1024
    if (idx < ADJ_V4) {
        ((uint4*)g_adj)[idx] = z;
    } else if (idx < ADJ_V4 + POOL_V4) {
        ((uint4*)g_pooled)[idx - ADJ_V4] = z;
    }
}

// ---------------------------------------------------------------------------
// 2) Edge scatter into bitmap: A[start, end_local] = 1 (dedup via bitmap)
// ---------------------------------------------------------------------------
__global__ void k_scatter(const void* ei_raw) {
    int e = blockIdx.x * blockDim.x + threadIdx.x;
    if (e >= EDGES) return;
    int s, t;
    if (g_is64) {
        const long long* p = (const long long*)ei_raw;
        s = (int)p[e];
        t = (int)p[EDGES + e];
    } else {
        const int* p = (const int*)ei_raw;
        s = p[e];
        t = p[EDGES + e];
    }
    int local = t & (N_ - 1);
    atomicOr(&g_adj[s * ROW_WORDS + (local >> 5)], 1u << (local & 31));
}

// ---------------------------------------------------------------------------
// 3) Fused: s[row] = sum_{j in N(row)} x[j];  y = s@W + bias;  max-pool
//    One warp per row. Lane l owns output dims {l, l+32}.
// ---------------------------------------------------------------------------
__global__ __launch_bounds__(256)
void k_aggregate(const float* __restrict__ x,
                 const float* __restrict__ W,
                 const float* __restrict__ bias) {
    __shared__ float2 Wsh[64 * 32];     // Wsh[k][lane] = {W[k][lane], W[k][lane+32]}  (16 KB)
    __shared__ float  ys[8][64];        // per-warp y for block max-reduce (2 KB)

    const int tid  = threadIdx.x;
    const int warp = tid >> 5;
    const int lane = tid & 31;

    // Stage W as float2 pairs
    for (int i = tid; i < 64 * 32; i += 256) {
        int k = i >> 5, l = i & 31;
        Wsh[i] = make_float2(W[k * 64 + l], W[k * 64 + l + 32]);
    }
    __syncthreads();

    const int row = blockIdx.x * 8 + warp;      // 8192 blocks * 8 warps = 65536 rows
    const int g   = row >> 10;                  // graph id (all warps in block share g)

    // --- gather neighbors from bitmap row ---
    unsigned word = g_adj[row * ROW_WORDS + lane];   // coalesced 128B per warp
    float acc0 = 0.f, acc1 = 0.f;
    unsigned ball = __ballot_sync(FULLMASK, word != 0);
    while (ball) {
        int src = __ffs(ball) - 1;
        ball &= ball - 1;
        unsigned w = __shfl_sync(FULLMASK, word, src);
        const float* xb = x + ((((long)g << 5) + src) << 11);  // (g*1024 + src*32) * 64
        while (w) {
            int b = __ffs(w) - 1;
            w &= w - 1;
            const float* xp = xb + (b << 6);
            acc0 += xp[lane];
            acc1 += xp[lane + 32];
        }
    }

    // --- y = s @ W + bias ---
    float y0 = __ldg(&bias[lane]);
    float y1 = __ldg(&bias[lane + 32]);
#pragma unroll
    for (int k = 0; k < 32; k++) {
        float s = __shfl_sync(FULLMASK, acc0, k);
        float2 w2 = Wsh[(k << 5) + lane];
        y0 = fmaf(s, w2.x, y0);
        y1 = fmaf(s, w2.y, y1);
    }
#pragma unroll
    for (int k = 0; k < 32; k++) {
        float s = __shfl_sync(FULLMASK, acc1, k);
        float2 w2 = Wsh[((k + 32) << 5) + lane];
        y0 = fmaf(s, w2.x, y0);
        y1 = fmaf(s, w2.y, y1);
    }

    // --- block max-reduce, then one atomicMax per dim per block ---
    ys[warp][lane]      = y0;
    ys[warp][lane + 32] = y1;
    __syncthreads();
    if (tid < 64) {
        float m = ys[0][tid];
#pragma unroll
        for (int w2i = 1; w2i < 8; w2i++) m = fmaxf(m, ys[w2i][tid]);
        atomicMax(&g_pooled[g * 64 + tid], fmap(m));
    }
}

// ---------------------------------------------------------------------------
// 4) MLP head: tanh(p@w1+b1) -> tanh(@w2+b2) -> @w3+b3.  One warp per graph.
// ---------------------------------------------------------------------------
__global__ __launch_bounds__(1024)
void k_mlp(const float* __restrict__ w1, const float* __restrict__ b1,
           const float* __restrict__ w2, const float* __restrict__ b2,
           const float* __restrict__ w3, const float* __restrict__ b3,
           float* __restrict__ out) {
    const int lane = threadIdx.x & 31;
    const int warp = threadIdx.x >> 5;
    const int gr   = blockIdx.x * 32 + warp;

    float h0 = funmap(g_pooled[gr * 64 + lane]);
    float h1 = funmap(g_pooled[gr * 64 + lane + 32]);

    // layer 1
    float a0 = __ldg(&b1[lane]), a1 = __ldg(&b1[lane + 32]);
#pragma unroll
    for (int k = 0; k < 32; k++) {
        float s = __shfl_sync(FULLMASK, h0, k);
        a0 = fmaf(s, __ldg(&w1[k * 64 + lane]),      a0);
        a1 = fmaf(s, __ldg(&w1[k * 64 + lane + 32]), a1);
    }
#pragma unroll
    for (int k = 0; k < 32; k++) {
        float s = __shfl_sync(FULLMASK, h1, k);
        a0 = fmaf(s, __ldg(&w1[(k + 32) * 64 + lane]),      a0);
        a1 = fmaf(s, __ldg(&w1[(k + 32) * 64 + lane + 32]), a1);
    }
    h0 = tanhf(a0);
    h1 = tanhf(a1);

    // layer 2
    a0 = __ldg(&b2[lane]); a1 = __ldg(&b2[lane + 32]);
#pragma unroll
    for (int k = 0; k < 32; k++) {
        float s = __shfl_sync(FULLMASK, h0, k);
        a0 = fmaf(s, __ldg(&w2[k * 64 + lane]),      a0);
        a1 = fmaf(s, __ldg(&w2[k * 64 + lane + 32]), a1);
    }
#pragma unroll
    for (int k = 0; k < 32; k++) {
        float s = __shfl_sync(FULLMASK, h1, k);
        a0 = fmaf(s, __ldg(&w2[(k + 32) * 64 + lane]),      a0);
        a1 = fmaf(s, __ldg(&w2[(k + 32) * 64 + lane + 32]), a1);
    }
    h0 = tanhf(a0);
    h1 = tanhf(a1);

    // layer 3: dot(h, w3) + b3
    float p = h0 * __ldg(&w3[lane]) + h1 * __ldg(&w3[lane + 32]);
#pragma unroll
    for (int o = 16; o; o >>= 1) p += __shfl_xor_sync(FULLMASK, p, o);
    if (lane == 0) out[gr] = p + __ldg(&b3[0]);
}

// ---------------------------------------------------------------------------
// Inputs (metadata order):
//  0:x [65536,64] f32   1:edge_index [2,E] int   2:batch (unused)
//  3:batch_size (unused) 4:weight [64,64] 5:bias [64]
//  6:w1 [64,64] 7:b1 [64] 8:w2 [64,64] 9:b2 [64] 10:w3 [64,1] 11:b3 [1]
// Output: [64,1] f32
// ---------------------------------------------------------------------------
extern "C" void kernel_launch(void* const* d_in, const int* in_sizes, int n_in,
                              void* d_out, int out_size) {
    const float* x      = (const float*)d_in[0];
    const void*  eidx   = d_in[1];
    const float* weight = (const float*)d_in[4];
    const float* bias   = (const float*)d_in[5];
    const float* w1     = (const float*)d_in[6];
    const float* b1     = (const float*)d_in[7];
    const float* w2     = (const float*)d_in[8];
    const float* b2     = (const float*)d_in[9];
    const float* w3     = (const float*)d_in[10];
    const float* b3     = (const float*)d_in[11];
    float* out = (float*)d_out;

    k_detect<<<1, 1>>>(eidx);

    constexpr unsigned CLEAR_V4 = ADJ_WORDS / 4 + (B_ * D_) / 4;   // 525312
    k_clear<<<(CLEAR_V4 + 255) / 256, 256>>>();

    k_scatter<<<EDGES / 256, 256>>>(eidx);

    k_aggregate<<<NNODES / 8, 256>>>(x, weight, bias);

    k_mlp<<<2, 1024>>>(w1, b1, w2, b2, w3, b3, out);
}

// round 5
// speedup vs baseline: 1.1285x; 1.1285x over previous
#include <cuda_runtime.h>
#include <cstdint>

#define FULLMASK 0xffffffffu

constexpr int B_   = 64;
constexpr int N_   = 1024;
constexpr int D_   = 64;
constexpr int NNODES = B_ * N_;                 // 65536
constexpr int EDGES  = 1 << 20;                 // 1,048,576
constexpr int ROW_WORDS = N_ / 32;              // 32
constexpr int ADJ_WORDS = NNODES * ROW_WORDS;   // 2,097,152 (8 MB)

constexpr int ROWS_PER_BLOCK = 128;
constexpr int THREADS = 256;                     // 8 warps, 16 rows/warp
constexpr int LISTCAP  = 320;                    // neighbor list cap per row (deg~Poisson(16))
constexpr int S_STRIDE = 66;                     // floats per S row (bank-friendly)
constexpr int W_STRIDE = 68;                     // floats per W row (16B-aligned rows)

// smem layout (floats):
constexpr int SM_S_OFF    = 0;                               // S[128][66]
constexpr int SM_W_OFF    = ROWS_PER_BLOCK * S_STRIDE;       // 8448
constexpr int SM_LIST_OFF = SM_W_OFF + 64 * W_STRIDE;        // 8448+4352=12800 (float idx)
constexpr int SM_BYTES    = SM_LIST_OFF * 4 + 8 * LISTCAP * 2;  // 51200 + 5120 = 56320

// Scratch (no allocations allowed)
__device__ unsigned g_adj[ADJ_WORDS];
__device__ unsigned g_pooled[B_ * D_];
__device__ int g_is64;

// Order-preserving float <-> uint map for atomicMax on floats
__device__ __forceinline__ unsigned fmap(float f) {
    unsigned u = __float_as_uint(f);
    return (u & 0x80000000u) ? ~u : (u | 0x80000000u);
}
__device__ __forceinline__ float funmap(unsigned u) {
    return (u & 0x80000000u) ? __uint_as_float(u ^ 0x80000000u)
                             : __uint_as_float(~u);
}

// ---- packed f32x2 helpers (Blackwell) ----
__device__ __forceinline__ unsigned long long pack2(float lo, float hi) {
    unsigned long long r;
    unsigned a = __float_as_uint(lo), b = __float_as_uint(hi);
    asm("mov.b64 %0, {%1, %2};" : "=l"(r) : "r"(a), "r"(b));
    return r;
}
__device__ __forceinline__ unsigned long long fma2(unsigned long long a,
                                                   unsigned long long b,
                                                   unsigned long long c) {
    unsigned long long d;
    asm("fma.rn.f32x2 %0, %1, %2, %3;" : "=l"(d) : "l"(a), "l"(b), "l"(c));
    return d;
}
__device__ __forceinline__ unsigned long long add2(unsigned long long a,
                                                   unsigned long long b) {
    unsigned long long d;
    asm("add.rn.f32x2 %0, %1, %2;" : "=l"(d) : "l"(a), "l"(b));
    return d;
}
__device__ __forceinline__ float lo2(unsigned long long u) { return __uint_as_float((unsigned)u); }
__device__ __forceinline__ float hi2(unsigned long long u) { return __uint_as_float((unsigned)(u >> 32)); }

union F4U {
    float4 f;
    unsigned long long u[2];
};

// W bank swizzle: chunk (4 floats) starting at dim dc placed at word p within a 68-word row.
// Upper-half chunks rotated by 4 words so the 8 chunks of one LDS.128 hit 8 distinct bank groups.
__device__ __host__ __forceinline__ int wphys(int dc) {
    return (dc < 32) ? dc : ((((dc + 4) & 31)) | 32);
}

// ---------------------------------------------------------------------------
// 1) Clear bitmap + pooled accumulator; fold in int64/int32 detection
// ---------------------------------------------------------------------------
__global__ void k_clear(const void* ei) {
    unsigned idx = blockIdx.x * blockDim.x + threadIdx.x;
    if (idx == 0) {
        const long long* p = (const long long*)ei;
        int is64 = 1;
        for (int i = 0; i < 16; i++) {
            long long v = p[i];
            if (v < 0 || v > 65535) is64 = 0;
        }
        g_is64 = is64;
    }
    const uint4 z = make_uint4(0, 0, 0, 0);
    constexpr unsigned ADJ_V4 = ADJ_WORDS / 4;
    constexpr unsigned POOL_V4 = (B_ * D_) / 4;
    if (idx < ADJ_V4) {
        ((uint4*)g_adj)[idx] = z;
    } else if (idx < ADJ_V4 + POOL_V4) {
        ((uint4*)g_pooled)[idx - ADJ_V4] = z;
    }
}

// ---------------------------------------------------------------------------
// 2) Edge scatter into bitmap (idempotent -> exact dedup of duplicate edges)
// ---------------------------------------------------------------------------
__global__ void k_scatter(const void* ei_raw) {
    int e = blockIdx.x * blockDim.x + threadIdx.x;
    if (e >= EDGES) return;
    int s, t;
    if (g_is64) {
        const long long* p = (const long long*)ei_raw;
        s = (int)p[e];
        t = (int)p[EDGES + e];
    } else {
        const int* p = (const int*)ei_raw;
        s = p[e];
        t = p[EDGES + e];
    }
    int local = t & (N_ - 1);
    atomicOr(&g_adj[s * ROW_WORDS + (local >> 5)], 1u << (local & 31));
}

// ---------------------------------------------------------------------------
// 3) Fused gather + transform + max-pool.
//    Block = 128 rows of one graph. Phase A: per-warp bitmap decode + half-warp
//    float4 gather -> S in smem. Phase B: register-blocked [128x64]@[64x64]
//    with f32x2 FMA, bias folded into accumulator init, max-pool epilogue.
// ---------------------------------------------------------------------------
__global__ __launch_bounds__(THREADS)
void k_aggregate(const float* __restrict__ x,
                 const float* __restrict__ W,
                 const float* __restrict__ bias) {
    extern __shared__ float smem[];
    float* S   = smem + SM_S_OFF;
    float* Wsh = smem + SM_W_OFF;
    unsigned short* listAll = (unsigned short*)(smem + SM_LIST_OFF);

    const int tid  = threadIdx.x;
    const int warp = tid >> 5;
    const int lane = tid & 31;
    const int g    = blockIdx.x >> 3;           // 128 rows/block, 1024 rows/graph

    // ---- stage W (swizzled) ----
    for (int idx = tid; idx < 64 * 64; idx += THREADS) {
        int k = idx >> 6, d = idx & 63;
        Wsh[k * W_STRIDE + wphys(d & ~3) + (d & 3)] = W[idx];
    }

    // ---- Phase A: gather ----
    {
        const int h   = lane >> 4;
        const int l16 = lane & 15;
        unsigned short* lst = listAll + warp * LISTCAP;
        const float* xg = x + ((size_t)g << 16);   // g * 65536 floats

        for (int i = 0; i < 16; i++) {
            const int lr   = warp * 16 + i;
            const int grow = blockIdx.x * ROWS_PER_BLOCK + lr;

            // decode bitmap row -> compact neighbor list
            unsigned word = g_adj[grow * ROW_WORDS + lane];
            int cnt = __popc(word);
            int pre = cnt;
#pragma unroll
            for (int o = 1; o < 32; o <<= 1) {
                int v = __shfl_up_sync(FULLMASK, pre, o);
                if (lane >= o) pre += v;
            }
            int deg = __shfl_sync(FULLMASK, pre, 31);
            pre -= cnt;
            while (word) {
                int b = __ffs(word) - 1;
                word &= word - 1;
                if (pre < LISTCAP) lst[pre] = (unsigned short)((lane << 5) | b);
                pre++;
            }
            if (deg > LISTCAP) deg = LISTCAP;
            __syncwarp();

            // half-warp pair gather: half h loads neighbor 2t+h, dims 4*l16..4*l16+3
            unsigned long long a0 = 0ull, a1 = 0ull;
            const int np = (deg + 1) >> 1;
            for (int t = 0; t < np; t++) {
                int ni = 2 * t + h;
                if (ni < deg) {
                    F4U v;
                    v.f = __ldg((const float4*)(xg + ((int)lst[ni] << 6) + (l16 << 2)));
                    a0 = add2(a0, v.u[0]);
                    a1 = add2(a1, v.u[1]);
                }
            }
            // combine halves
            float s0 = lo2(a0), s1 = hi2(a0), s2 = lo2(a1), s3 = hi2(a1);
            s0 += __shfl_xor_sync(FULLMASK, s0, 16);
            s1 += __shfl_xor_sync(FULLMASK, s1, 16);
            s2 += __shfl_xor_sync(FULLMASK, s2, 16);
            s3 += __shfl_xor_sync(FULLMASK, s3, 16);
            if (h == 0) {
                float* Srow = &S[lr * S_STRIDE + 4 * l16];
                Srow[0] = s0; Srow[1] = s1; Srow[2] = s2; Srow[3] = s3;
            }
            __syncwarp();
        }
    }
    __syncthreads();

    // ---- Phase B: Y = S@W + bias, register-blocked 4 rows x 8 dims / thread ----
    const int d0    = (lane & 7) * 8;
    const int rsub  = lane >> 3;
    const int rbase = warp * 16 + rsub * 4;
    const int pc0   = wphys(d0);
    const int pc1   = wphys(d0 + 4);

    unsigned long long acc[4][4];
    {
        unsigned long long bp[4];
#pragma unroll
        for (int p = 0; p < 4; p++)
            bp[p] = pack2(__ldg(&bias[d0 + 2 * p]), __ldg(&bias[d0 + 2 * p + 1]));
#pragma unroll
        for (int i = 0; i < 4; i++)
#pragma unroll
            for (int p = 0; p < 4; p++) acc[i][p] = bp[p];
    }

#pragma unroll 8
    for (int k = 0; k < 64; k++) {
        F4U wa, wb;
        wa.f = *reinterpret_cast<const float4*>(&Wsh[k * W_STRIDE + pc0]);
        wb.f = *reinterpret_cast<const float4*>(&Wsh[k * W_STRIDE + pc1]);
#pragma unroll
        for (int i = 0; i < 4; i++) {
            float s = S[(rbase + i) * S_STRIDE + k];
            unsigned long long sp = pack2(s, s);
            acc[i][0] = fma2(sp, wa.u[0], acc[i][0]);
            acc[i][1] = fma2(sp, wa.u[1], acc[i][1]);
            acc[i][2] = fma2(sp, wb.u[0], acc[i][2]);
            acc[i][3] = fma2(sp, wb.u[1], acc[i][3]);
        }
    }

    // ---- max-pool epilogue ----
    float m[8];
#pragma unroll
    for (int p = 0; p < 4; p++) {
        float m0 = lo2(acc[0][p]), m1 = hi2(acc[0][p]);
#pragma unroll
        for (int i = 1; i < 4; i++) {
            m0 = fmaxf(m0, lo2(acc[i][p]));
            m1 = fmaxf(m1, hi2(acc[i][p]));
        }
        m[2 * p] = m0;
        m[2 * p + 1] = m1;
    }
#pragma unroll
    for (int j = 0; j < 8; j++) {
        m[j] = fmaxf(m[j], __shfl_xor_sync(FULLMASK, m[j], 8));
        m[j] = fmaxf(m[j], __shfl_xor_sync(FULLMASK, m[j], 16));
    }
    if (rsub == 0) {
#pragma unroll
        for (int j = 0; j < 8; j++)
            atomicMax(&g_pooled[g * 64 + d0 + j], fmap(m[j]));
    }
}

// ---------------------------------------------------------------------------
// 4) MLP head: tanh(p@w1+b1) -> tanh(@w2+b2) -> @w3+b3.  One warp per graph.
// ---------------------------------------------------------------------------
__global__ __launch_bounds__(1024)
void k_mlp(const float* __restrict__ w1, const float* __restrict__ b1,
           const float* __restrict__ w2, const float* __restrict__ b2,
           const float* __restrict__ w3, const float* __restrict__ b3,
           float* __restrict__ out) {
    const int lane = threadIdx.x & 31;
    const int warp = threadIdx.x >> 5;
    const int gr   = blockIdx.x * 32 + warp;

    float h0 = funmap(g_pooled[gr * 64 + lane]);
    float h1 = funmap(g_pooled[gr * 64 + lane + 32]);

    float a0 = __ldg(&b1[lane]), a1 = __ldg(&b1[lane + 32]);
#pragma unroll
    for (int k = 0; k < 32; k++) {
        float s = __shfl_sync(FULLMASK, h0, k);
        a0 = fmaf(s, __ldg(&w1[k * 64 + lane]),      a0);
        a1 = fmaf(s, __ldg(&w1[k * 64 + lane + 32]), a1);
    }
#pragma unroll
    for (int k = 0; k < 32; k++) {
        float s = __shfl_sync(FULLMASK, h1, k);
        a0 = fmaf(s, __ldg(&w1[(k + 32) * 64 + lane]),      a0);
        a1 = fmaf(s, __ldg(&w1[(k + 32) * 64 + lane + 32]), a1);
    }
    h0 = tanhf(a0);
    h1 = tanhf(a1);

    a0 = __ldg(&b2[lane]); a1 = __ldg(&b2[lane + 32]);
#pragma unroll
    for (int k = 0; k < 32; k++) {
        float s = __shfl_sync(FULLMASK, h0, k);
        a0 = fmaf(s, __ldg(&w2[k * 64 + lane]),      a0);
        a1 = fmaf(s, __ldg(&w2[k * 64 + lane + 32]), a1);
    }
#pragma unroll
    for (int k = 0; k < 32; k++) {
        float s = __shfl_sync(FULLMASK, h1, k);
        a0 = fmaf(s, __ldg(&w2[(k + 32) * 64 + lane]),      a0);
        a1 = fmaf(s, __ldg(&w2[(k + 32) * 64 + lane + 32]), a1);
    }
    h0 = tanhf(a0);
    h1 = tanhf(a1);

    float p = h0 * __ldg(&w3[lane]) + h1 * __ldg(&w3[lane + 32]);
#pragma unroll
    for (int o = 16; o; o >>= 1) p += __shfl_xor_sync(FULLMASK, p, o);
    if (lane == 0) out[gr] = p + __ldg(&b3[0]);
}

// ---------------------------------------------------------------------------
extern "C" void kernel_launch(void* const* d_in, const int* in_sizes, int n_in,
                              void* d_out, int out_size) {
    const float* x      = (const float*)d_in[0];
    const void*  eidx   = d_in[1];
    const float* weight = (const float*)d_in[4];
    const float* bias   = (const float*)d_in[5];
    const float* w1     = (const float*)d_in[6];
    const float* b1     = (const float*)d_in[7];
    const float* w2     = (const float*)d_in[8];
    const float* b2     = (const float*)d_in[9];
    const float* w3     = (const float*)d_in[10];
    const float* b3     = (const float*)d_in[11];
    float* out = (float*)d_out;

    cudaFuncSetAttribute(k_aggregate, cudaFuncAttributeMaxDynamicSharedMemorySize, SM_BYTES);

    constexpr unsigned CLEAR_V4 = ADJ_WORDS / 4 + (B_ * D_) / 4;
    k_clear<<<(CLEAR_V4 + 255) / 256, 256>>>(eidx);

    k_scatter<<<EDGES / 256, 256>>>(eidx);

    k_aggregate<<<NNODES / ROWS_PER_BLOCK, THREADS, SM_BYTES>>>(x, weight, bias);

    k_mlp<<<2, 1024>>>(w1, b1, w2, b2, w3, b3, out);
}

// round 6
// speedup vs baseline: 1.7164x; 1.5209x over previous
#include <cuda_runtime.h>
#include <cstdint>

#define FULLMASK 0xffffffffu

constexpr int B_   = 64;
constexpr int N_   = 1024;
constexpr int D_   = 64;
constexpr int NNODES = B_ * N_;                 // 65536
constexpr int EDGES  = 1 << 20;                 // 1,048,576
constexpr int ROW_WORDS = N_ / 32;              // 32
constexpr int ADJ_WORDS = NNODES * ROW_WORDS;   // 2,097,152 (8 MB)

constexpr int ROWS_PER_BLOCK = 128;
constexpr int THREADS = 256;                     // 8 warps, 16 rows/warp
constexpr int LISTCAP  = 320;                    // neighbor list cap per row
constexpr int S_STRIDE = 66;                     // floats per S row
constexpr int W_STRIDE = 68;                     // floats per W row

// smem layout (floats):
constexpr int SM_S_OFF    = 0;                               // S[128][66]
constexpr int SM_W_OFF    = ROWS_PER_BLOCK * S_STRIDE;       // 8448
constexpr int SM_LIST_OFF = SM_W_OFF + 64 * W_STRIDE;        // 12800
constexpr int SM_BYTES    = SM_LIST_OFF * 4 + 8 * LISTCAP * 2;  // 56320

// Scratch
__device__ unsigned g_adj[ADJ_WORDS];
__device__ unsigned g_pooled[B_ * D_];
__device__ int g_is64;

// Order-preserving float <-> uint map for atomicMax on floats
__device__ __forceinline__ unsigned fmap(float f) {
    unsigned u = __float_as_uint(f);
    return (u & 0x80000000u) ? ~u : (u | 0x80000000u);
}
__device__ __forceinline__ float funmap(unsigned u) {
    return (u & 0x80000000u) ? __uint_as_float(u ^ 0x80000000u)
                             : __uint_as_float(~u);
}

// ---- packed f32x2 helpers (Blackwell) ----
__device__ __forceinline__ unsigned long long pack2(float lo, float hi) {
    unsigned long long r;
    unsigned a = __float_as_uint(lo), b = __float_as_uint(hi);
    asm("mov.b64 %0, {%1, %2};" : "=l"(r) : "r"(a), "r"(b));
    return r;
}
__device__ __forceinline__ unsigned long long fma2(unsigned long long a,
                                                   unsigned long long b,
                                                   unsigned long long c) {
    unsigned long long d;
    asm("fma.rn.f32x2 %0, %1, %2, %3;" : "=l"(d) : "l"(a), "l"(b), "l"(c));
    return d;
}
__device__ __forceinline__ unsigned long long add2(unsigned long long a,
                                                   unsigned long long b) {
    unsigned long long d;
    asm("add.rn.f32x2 %0, %1, %2;" : "=l"(d) : "l"(a), "l"(b));
    return d;
}
__device__ __forceinline__ float lo2(unsigned long long u) { return __uint_as_float((unsigned)u); }
__device__ __forceinline__ float hi2(unsigned long long u) { return __uint_as_float((unsigned)(u >> 32)); }

union F4U {
    float4 f;
    unsigned long long u[2];
};

// W bank swizzle: 4-float chunks; upper-half chunks rotated by 4 words
__device__ __host__ __forceinline__ int wphys(int dc) {
    return (dc < 32) ? dc : ((((dc + 4) & 31)) | 32);
}

// ---------------------------------------------------------------------------
// 1) Clear bitmap + pooled accumulator; fold in int64/int32 detection
// ---------------------------------------------------------------------------
__global__ void k_clear(const void* ei) {
    unsigned idx = blockIdx.x * blockDim.x + threadIdx.x;
    if (idx == 0) {
        const long long* p = (const long long*)ei;
        int is64 = 1;
        for (int i = 0; i < 16; i++) {
            long long v = p[i];
            if (v < 0 || v > 65535) is64 = 0;
        }
        g_is64 = is64;
    }
    const uint4 z = make_uint4(0, 0, 0, 0);
    constexpr unsigned ADJ_V4 = ADJ_WORDS / 4;
    constexpr unsigned POOL_V4 = (B_ * D_) / 4;
    if (idx < ADJ_V4) {
        ((uint4*)g_adj)[idx] = z;
    } else if (idx < ADJ_V4 + POOL_V4) {
        ((uint4*)g_pooled)[idx - ADJ_V4] = z;
    }
}

// ---------------------------------------------------------------------------
// 2) Edge scatter into bitmap (idempotent -> exact dedup)
// ---------------------------------------------------------------------------
__global__ void k_scatter(const void* ei_raw) {
    int e = blockIdx.x * blockDim.x + threadIdx.x;
    if (e >= EDGES) return;
    int s, t;
    if (g_is64) {
        const long long* p = (const long long*)ei_raw;
        s = (int)p[e];
        t = (int)p[EDGES + e];
    } else {
        const int* p = (const int*)ei_raw;
        s = p[e];
        t = p[EDGES + e];
    }
    int local = t & (N_ - 1);
    atomicOr(&g_adj[s * ROW_WORDS + (local >> 5)], 1u << (local & 31));
}

// ---------------------------------------------------------------------------
// 3) Fused gather + transform + max-pool.
// ---------------------------------------------------------------------------
__global__ __launch_bounds__(THREADS)
void k_aggregate(const float* __restrict__ x,
                 const float* __restrict__ W,
                 const float* __restrict__ bias) {
    extern __shared__ float smem[];
    float* S   = smem + SM_S_OFF;
    float* Wsh = smem + SM_W_OFF;
    unsigned short* listAll = (unsigned short*)(smem + SM_LIST_OFF);

    const int tid  = threadIdx.x;
    const int warp = tid >> 5;
    const int lane = tid & 31;
    const int g    = blockIdx.x >> 3;

    // ---- stage W (swizzled) ----
    for (int idx = tid; idx < 64 * 64; idx += THREADS) {
        int k = idx >> 6, d = idx & 63;
        Wsh[k * W_STRIDE + wphys(d & ~3) + (d & 3)] = W[idx];
    }

    // ---- Phase A: gather ----
    {
        const int h   = lane >> 4;
        const int l16 = lane & 15;
        const int off = l16 << 2;
        unsigned short* lst = listAll + warp * LISTCAP;
        const float* xg = x + ((size_t)g << 16);

        const int rowBase = blockIdx.x * ROWS_PER_BLOCK + warp * 16;
        unsigned wordNext = g_adj[rowBase * ROW_WORDS + lane];

        for (int i = 0; i < 16; i++) {
            const int lr = warp * 16 + i;
            unsigned word = wordNext;
            if (i < 15)
                wordNext = g_adj[(rowBase + i + 1) * ROW_WORDS + lane];

            // decode bitmap row -> compact neighbor list
            int cnt = __popc(word);
            int pre = cnt;
#pragma unroll
            for (int o = 1; o < 32; o <<= 1) {
                int v = __shfl_up_sync(FULLMASK, pre, o);
                if (lane >= o) pre += v;
            }
            int deg = __shfl_sync(FULLMASK, pre, 31);
            pre -= cnt;
            while (word) {
                int b = __ffs(word) - 1;
                word &= word - 1;
                if (pre < LISTCAP) lst[pre] = (unsigned short)((lane << 5) | b);
                pre++;
            }
            if (deg > LISTCAP) deg = LISTCAP;
            __syncwarp();

            // half-warp pair gather, unrolled x4 with two accumulator chains
            unsigned long long a0 = 0ull, a1 = 0ull, b0 = 0ull, b1 = 0ull;
            const int nfull = deg >> 1;          // complete pairs
            int t = 0;
            for (; t + 4 <= nfull; t += 4) {
                int i0 = (int)lst[2 * t + h];
                int i1 = (int)lst[2 * (t + 1) + h];
                int i2 = (int)lst[2 * (t + 2) + h];
                int i3 = (int)lst[2 * (t + 3) + h];
                F4U v0, v1, v2, v3;
                v0.f = __ldg((const float4*)(xg + (i0 << 6) + off));
                v1.f = __ldg((const float4*)(xg + (i1 << 6) + off));
                v2.f = __ldg((const float4*)(xg + (i2 << 6) + off));
                v3.f = __ldg((const float4*)(xg + (i3 << 6) + off));
                a0 = add2(a0, v0.u[0]); a1 = add2(a1, v0.u[1]);
                b0 = add2(b0, v1.u[0]); b1 = add2(b1, v1.u[1]);
                a0 = add2(a0, v2.u[0]); a1 = add2(a1, v2.u[1]);
                b0 = add2(b0, v3.u[0]); b1 = add2(b1, v3.u[1]);
            }
            for (; t < nfull; t++) {
                int ni = (int)lst[2 * t + h];
                F4U v;
                v.f = __ldg((const float4*)(xg + (ni << 6) + off));
                a0 = add2(a0, v.u[0]);
                a1 = add2(a1, v.u[1]);
            }
            if ((deg & 1) && h == 0) {           // odd tail: handled by half 0
                int ni = (int)lst[deg - 1];
                F4U v;
                v.f = __ldg((const float4*)(xg + (ni << 6) + off));
                b0 = add2(b0, v.u[0]);
                b1 = add2(b1, v.u[1]);
            }
            a0 = add2(a0, b0);
            a1 = add2(a1, b1);

            // combine halves
            float s0 = lo2(a0), s1 = hi2(a0), s2 = lo2(a1), s3 = hi2(a1);
            s0 += __shfl_xor_sync(FULLMASK, s0, 16);
            s1 += __shfl_xor_sync(FULLMASK, s1, 16);
            s2 += __shfl_xor_sync(FULLMASK, s2, 16);
            s3 += __shfl_xor_sync(FULLMASK, s3, 16);
            if (h == 0) {
                float* Srow = &S[lr * S_STRIDE + 4 * l16];
                Srow[0] = s0; Srow[1] = s1; Srow[2] = s2; Srow[3] = s3;
            }
            __syncwarp();
        }
    }
    __syncthreads();

    // ---- Phase B: Y = S@W + bias, 4 rows x 8 dims / thread, f32x2 ----
    const int d0    = (lane & 7) * 8;
    const int rsub  = lane >> 3;
    const int rbase = warp * 16 + rsub * 4;
    const int pc0   = wphys(d0);
    const int pc1   = wphys(d0 + 4);

    unsigned long long acc[4][4];
    {
        unsigned long long bp[4];
#pragma unroll
        for (int p = 0; p < 4; p++)
            bp[p] = pack2(__ldg(&bias[d0 + 2 * p]), __ldg(&bias[d0 + 2 * p + 1]));
#pragma unroll
        for (int i = 0; i < 4; i++)
#pragma unroll
            for (int p = 0; p < 4; p++) acc[i][p] = bp[p];
    }

#pragma unroll 8
    for (int k = 0; k < 64; k++) {
        F4U wa, wb;
        wa.f = *reinterpret_cast<const float4*>(&Wsh[k * W_STRIDE + pc0]);
        wb.f = *reinterpret_cast<const float4*>(&Wsh[k * W_STRIDE + pc1]);
#pragma unroll
        for (int i = 0; i < 4; i++) {
            float s = S[(rbase + i) * S_STRIDE + k];
            unsigned long long sp = pack2(s, s);
            acc[i][0] = fma2(sp, wa.u[0], acc[i][0]);
            acc[i][1] = fma2(sp, wa.u[1], acc[i][1]);
            acc[i][2] = fma2(sp, wb.u[0], acc[i][2]);
            acc[i][3] = fma2(sp, wb.u[1], acc[i][3]);
        }
    }

    // ---- max-pool epilogue ----
    float m[8];
#pragma unroll
    for (int p = 0; p < 4; p++) {
        float m0 = lo2(acc[0][p]), m1 = hi2(acc[0][p]);
#pragma unroll
        for (int i = 1; i < 4; i++) {
            m0 = fmaxf(m0, lo2(acc[i][p]));
            m1 = fmaxf(m1, hi2(acc[i][p]));
        }
        m[2 * p] = m0;
        m[2 * p + 1] = m1;
    }
#pragma unroll
    for (int j = 0; j < 8; j++) {
        m[j] = fmaxf(m[j], __shfl_xor_sync(FULLMASK, m[j], 8));
        m[j] = fmaxf(m[j], __shfl_xor_sync(FULLMASK, m[j], 16));
    }
    if (rsub == 0) {
#pragma unroll
        for (int j = 0; j < 8; j++)
            atomicMax(&g_pooled[g * 64 + d0 + j], fmap(m[j]));
    }
}

// ---------------------------------------------------------------------------
// 4) MLP head: one warp per graph, one block per graph (spread across SMs)
// ---------------------------------------------------------------------------
__global__ __launch_bounds__(32)
void k_mlp(const float* __restrict__ w1, const float* __restrict__ b1,
           const float* __restrict__ w2, const float* __restrict__ b2,
           const float* __restrict__ w3, const float* __restrict__ b3,
           float* __restrict__ out) {
    const int lane = threadIdx.x;
    const int gr   = blockIdx.x;

    float h0 = funmap(g_pooled[gr * 64 + lane]);
    float h1 = funmap(g_pooled[gr * 64 + lane + 32]);

    float a0 = __ldg(&b1[lane]), a1 = __ldg(&b1[lane + 32]);
#pragma unroll
    for (int k = 0; k < 32; k++) {
        float s = __shfl_sync(FULLMASK, h0, k);
        a0 = fmaf(s, __ldg(&w1[k * 64 + lane]),      a0);
        a1 = fmaf(s, __ldg(&w1[k * 64 + lane + 32]), a1);
    }
#pragma unroll
    for (int k = 0; k < 32; k++) {
        float s = __shfl_sync(FULLMASK, h1, k);
        a0 = fmaf(s, __ldg(&w1[(k + 32) * 64 + lane]),      a0);
        a1 = fmaf(s, __ldg(&w1[(k + 32) * 64 + lane + 32]), a1);
    }
    h0 = tanhf(a0);
    h1 = tanhf(a1);

    a0 = __ldg(&b2[lane]); a1 = __ldg(&b2[lane + 32]);
#pragma unroll
    for (int k = 0; k < 32; k++) {
        float s = __shfl_sync(FULLMASK, h0, k);
        a0 = fmaf(s, __ldg(&w2[k * 64 + lane]),      a0);
        a1 = fmaf(s, __ldg(&w2[k * 64 + lane + 32]), a1);
    }
#pragma unroll
    for (int k = 0; k < 32; k++) {
        float s = __shfl_sync(FULLMASK, h1, k);
        a0 = fmaf(s, __ldg(&w2[(k + 32) * 64 + lane]),      a0);
        a1 = fmaf(s, __ldg(&w2[(k + 32) * 64 + lane + 32]), a1);
    }
    h0 = tanhf(a0);
    h1 = tanhf(a1);

    float p = h0 * __ldg(&w3[lane]) + h1 * __ldg(&w3[lane + 32]);
#pragma unroll
    for (int o = 16; o; o >>= 1) p += __shfl_xor_sync(FULLMASK, p, o);
    if (lane == 0) out[gr] = p + __ldg(&b3[0]);
}

// ---------------------------------------------------------------------------
extern "C" void kernel_launch(void* const* d_in, const int* in_sizes, int n_in,
                              void* d_out, int out_size) {
    const float* x      = (const float*)d_in[0];
    const void*  eidx   = d_in[1];
    const float* weight = (const float*)d_in[4];
    const float* bias   = (const float*)d_in[5];
    const float* w1     = (const float*)d_in[6];
    const float* b1     = (const float*)d_in[7];
    const float* w2     = (const float*)d_in[8];
    const float* b2     = (const float*)d_in[9];
    const float* w3     = (const float*)d_in[10];
    const float* b3     = (const float*)d_in[11];
    float* out = (float*)d_out;

    cudaFuncSetAttribute(k_aggregate, cudaFuncAttributeMaxDynamicSharedMemorySize, SM_BYTES);

    constexpr unsigned CLEAR_V4 = ADJ_WORDS / 4 + (B_ * D_) / 4;
    k_clear<<<(CLEAR_V4 + 255) / 256, 256>>>(eidx);

    k_scatter<<<EDGES / 256, 256>>>(eidx);

    k_aggregate<<<NNODES / ROWS_PER_BLOCK, THREADS, SM_BYTES>>>(x, weight, bias);

    k_mlp<<<B_, 32>>>(w1, b1, w2, b2, w3, b3, out);
}